// round 15
// baseline (speedup 1.0000x reference)
#include <cuda_runtime.h>
#include <cstdint>

// x: [32, 512, 56, 56] fp32, chunks of 8 batches (51.4 MB, L2-resident).
// 5 launches, NO excite kernels, NO post-streaming fences:
//   R0         : reduce chunk0 -> raw sums (plain stores, proven 6.28 TB/s
//                shape); blocks 0..95 zero chunks 1-3 raw sums (replay-safe).
//   SA(c, c+1) : prologue (per block, redundant): FC1 for the block's batch
//                from d_sq (+1/3136), FC2+sigmoid for the block's <=3 slices
//                -> e_s[]; barriers BEFORE streaming only.
//                streaming: coalesced scale chunk c (L2 reads + DRAM writes)
//                + fused reduce-accumulate chunk c+1 (DRAM reads -> prime L2,
//                segmented warp reduction + atomicAdd into raw sums).
// DRAM total: 410 MB vs 616 MB unchunked.

#define C            512
#define CR           32
#define SPATIAL4     784                        // f4 per slice
#define CHUNK_B      8
#define NCHUNK       4
#define CHUNK_SLICES 4096
#define CHUNK_F4     (CHUNK_SLICES * SPATIAL4)  // 3,211,264
#define NBLK         3136                       // CHUNK_F4 / 1024
#define BLKS_PER_BATCH_SA 392                   // 401408 f4 / 1024

__device__ float d_sq[32 * C];                  // raw per-slice sums

// ---------------------------------------------------------------------------
// R0: one block per slice of chunk 0 (proven shape). Also zeroes chunks 1-3
// raw sums so SA stages can accumulate atomically (replay-safe: runs first).
// ---------------------------------------------------------------------------
__global__ __launch_bounds__(128) void se_reduce0(const float* __restrict__ x)
{
    const int s = blockIdx.x;                   // slice in chunk 0

    if (blockIdx.x < 96)                        // zero 3*4096 floats
        d_sq[CHUNK_SLICES + blockIdx.x * 128 + threadIdx.x] = 0.0f;

    const float4* __restrict__ p =
        reinterpret_cast<const float4*>(x) + (size_t)s * SPATIAL4;

    float acc = 0.0f;
    #pragma unroll
    for (int i = threadIdx.x; i < SPATIAL4; i += 128) {
        float4 v = p[i];
        acc += (v.x + v.y) + (v.z + v.w);
    }
    #pragma unroll
    for (int off = 16; off > 0; off >>= 1)
        acc += __shfl_down_sync(0xFFFFFFFFu, acc, off);

    __shared__ float ws[4];
    const int lane = threadIdx.x & 31;
    if (lane == 0) ws[threadIdx.x >> 5] = acc;
    __syncthreads();
    if (threadIdx.x == 0)
        d_sq[s] = ws[0] + ws[1] + ws[2] + ws[3];
}

// ---------------------------------------------------------------------------
// SA: prologue (FC1+FC2 -> e_s) then streaming (R11-proven). No tails.
// ---------------------------------------------------------------------------
__global__ __launch_bounds__(256) void se_scale_accum(
    const float* __restrict__ x,
    float* __restrict__ out,
    const float* __restrict__ w1, const float* __restrict__ b1,
    const float* __restrict__ w2, const float* __restrict__ b2,
    int sc, int rc)
{
    const int tid  = threadIdx.x;
    const int lane = tid & 31;
    const int wid  = tid >> 5;                  // 8 warps

    // ---------------- prologue: excitation for this block's batch ----------
    __shared__ float hid[CR];
    __shared__ float e_s[3];

    const int batch = blockIdx.x / BLKS_PER_BATCH_SA;    // local batch 0..7
    const int gb    = sc * CHUNK_B + batch;              // global batch
    const float* __restrict__ sqp = d_sq + (size_t)gb * C;

    // FC1: warp w computes hidden units 4w..4w+3
    #pragma unroll
    for (int r = 0; r < 4; ++r) {
        const int u = wid * 4 + r;
        const float* __restrict__ wrow = w1 + (size_t)u * C;
        float a = 0.0f;
        #pragma unroll
        for (int k = 0; k < 16; ++k) {
            const int idx = lane + 32 * k;
            a = fmaf(__ldcg(&sqp[idx]), __ldg(&wrow[idx]), a);
        }
        #pragma unroll
        for (int off = 16; off > 0; off >>= 1)
            a += __shfl_down_sync(0xFFFFFFFFu, a, off);
        if (lane == 0)
            hid[u] = fmaxf(a * (1.0f / 3136.0f) + __ldg(&b1[u]), 0.0f);
    }
    __syncthreads();

    // FC2 + sigmoid for the block's <=3 slices
    const unsigned int i0b = blockIdx.x * 1024u;
    const int slice_lo = (int)(i0b / 784u);
    const int nsl      = (int)((i0b + 1023u) / 784u) - slice_lo + 1;
    if (tid < nsl) {
        const int sl = slice_lo + tid;                   // chunk-relative
        const int ch = sl & (C - 1);
        float a = __ldg(&b2[ch]);
        const float4* __restrict__ w2v =
            reinterpret_cast<const float4*>(w2 + (size_t)ch * CR);
        #pragma unroll
        for (int j = 0; j < CR / 4; ++j) {
            const float4 w = __ldg(&w2v[j]);
            a = fmaf(hid[4 * j + 0], w.x, a);
            a = fmaf(hid[4 * j + 1], w.y, a);
            a = fmaf(hid[4 * j + 2], w.z, a);
            a = fmaf(hid[4 * j + 3], w.w, a);
        }
        e_s[tid] = 1.0f / (1.0f + __expf(-a));
    }
    __syncthreads();

    // ---------------- streaming (R11 shape, nothing after stores) ----------
    const unsigned int i0 = i0b + tid;                   // chunk-relative f4
    const float4* __restrict__ x4 = reinterpret_cast<const float4*>(x);
    float4*       __restrict__ o4 = reinterpret_cast<float4*>(out);

    const unsigned int base_s = (unsigned int)sc * CHUNK_F4 + i0;

    float4 vs[4];
    #pragma unroll
    for (int j = 0; j < 4; ++j)
        vs[j] = __ldcs(x4 + base_s + j * 256u);

    float sred[4];
    if (rc >= 0) {
        const unsigned int base_r = (unsigned int)rc * CHUNK_F4 + i0;
        #pragma unroll
        for (int j = 0; j < 4; ++j) {
            const float4 v = x4[base_r + j * 256u];      // default: keep in L2
            sred[j] = (v.x + v.y) + (v.z + v.w);
        }
    }

    #pragma unroll
    for (int j = 0; j < 4; ++j) {
        const float e = e_s[(i0 + j * 256u) / 784u - slice_lo];
        float4 r = vs[j];
        r.x *= e; r.y *= e; r.z *= e; r.w *= e;
        __stcs(o4 + base_s + j * 256u, r);
    }

    if (rc >= 0) {
        #pragma unroll
        for (int j = 0; j < 4; ++j) {
            float s  = sred[j];
            int  key = (int)((i0 + j * 256u) / 784u);    // chunk-relative slice
            #pragma unroll
            for (int off = 16; off > 0; off >>= 1) {
                const float v2 = __shfl_down_sync(0xFFFFFFFFu, s, off);
                const int   k2 = __shfl_down_sync(0xFFFFFFFFu, key, off);
                if (lane + off < 32 && k2 == key) s += v2;
            }
            const int keyprev = __shfl_up_sync(0xFFFFFFFFu, key, 1);
            if (lane == 0 || keyprev != key)
                atomicAdd(&d_sq[rc * CHUNK_SLICES + key], s);
        }
    }
}

// ---------------------------------------------------------------------------
extern "C" void kernel_launch(void* const* d_in, const int* in_sizes, int n_in,
                              void* d_out, int out_size) {
    const float* x  = (const float*)d_in[0];
    const float* w1 = (const float*)d_in[1];
    const float* b1 = (const float*)d_in[2];
    const float* w2 = (const float*)d_in[3];
    const float* b2 = (const float*)d_in[4];
    float* out = (float*)d_out;

    se_reduce0<<<CHUNK_SLICES, 128>>>(x);
    for (int c = 0; c < NCHUNK; ++c) {
        const int rc = (c + 1 < NCHUNK) ? c + 1 : -1;
        se_scale_accum<<<NBLK, 256>>>(x, out, w1, b1, w2, b2, c, rc);
    }
}